// round 12
// baseline (speedup 1.0000x reference)
#include <cuda_runtime.h>
#include <cstdint>

// ---------------------------------------------------------------------------
// Problem constants
// ---------------------------------------------------------------------------
#define BATCH 8
#define IMG   256
#define CCH   16
#define HID   128
#define NPIX  (BATCH * IMG * IMG)
#define STATE_ELEMS (NPIX * CCH)
#define STEPS 32
#define LIST_CAP (NPIX / 2 + 8192)
#define NSM_BLOCKS 148

typedef unsigned long long u64;

__device__ float g_state[2][STATE_ELEMS];
__device__ int g_list[STEPS][LIST_CAP];
__device__ int g_ilist[STEPS][LIST_CAP];
__device__ int g_cnt[STEPS];
__device__ int g_icnt[STEPS];
// W0^T split into tf32 hi/lo: [n=128][k=48]
__device__ float g_w0t_hi[HID * 48];
__device__ float g_w0t_lo[HID * 48];

struct KeyArr { uint32_t k0[STEPS]; uint32_t k1[STEPS]; };

// ---------------------------------------------------------------------------
// packed f32x2 helpers (bit-exact: two independent rn fp32 FMAs)
// ---------------------------------------------------------------------------
static __device__ __forceinline__ u64 pack2dup(float x) {
    u64 r; asm("mov.b64 %0, {%1, %1};" : "=l"(r) : "f"(x)); return r;
}
static __device__ __forceinline__ void ffma2(u64& acc, u64 a, u64 b) {
    asm("fma.rn.f32x2 %0, %1, %2, %0;" : "+l"(acc) : "l"(a), "l"(b));
}
static __device__ __forceinline__ float2 unpack2(u64 v) {
    float2 f; asm("mov.b64 {%0, %1}, %2;" : "=f"(f.x), "=f"(f.y) : "l"(v)); return f;
}

// ---------------------------------------------------------------------------
// tf32 split
// ---------------------------------------------------------------------------
static __device__ __forceinline__ uint32_t cvt_tf32(float v) {
    uint32_t r; asm("cvt.rna.tf32.f32 %0, %1;" : "=r"(r) : "f"(v)); return r;
}
static __device__ __forceinline__ void split_tf32(float v, uint32_t& hi, uint32_t& lo) {
    hi = cvt_tf32(v);
    lo = cvt_tf32(v - __uint_as_float(hi));
}

// ---------------------------------------------------------------------------
// warp mma: m16n8k8 tf32 (sm_80 baseline PTX — legal on sm_103)
// ---------------------------------------------------------------------------
static __device__ __forceinline__ void mma_tf32(
    float* d, const uint32_t* a, uint32_t b0, uint32_t b1)
{
    asm volatile(
        "mma.sync.aligned.m16n8k8.row.col.f32.tf32.tf32.f32 "
        "{%0,%1,%2,%3},{%4,%5,%6,%7},{%8,%9},{%0,%1,%2,%3};"
        : "+f"(d[0]), "+f"(d[1]), "+f"(d[2]), "+f"(d[3])
        : "r"(a[0]), "r"(a[1]), "r"(a[2]), "r"(a[3]), "r"(b0), "r"(b1));
}

// ---------------------------------------------------------------------------
// Threefry-2x32 — exact JAX
// ---------------------------------------------------------------------------
static __host__ __device__ __forceinline__ uint32_t tf_rotl(uint32_t v, int r) {
    return (v << r) | (v >> (32 - r));
}
static __host__ __device__ __forceinline__ void threefry2x32(
    uint32_t k0, uint32_t k1, uint32_t x0, uint32_t x1,
    uint32_t& o0, uint32_t& o1)
{
    uint32_t ks2 = k0 ^ k1 ^ 0x1BD11BDAu;
    x0 += k0; x1 += k1;
    x0 += x1; x1 = tf_rotl(x1, 13); x1 ^= x0;
    x0 += x1; x1 = tf_rotl(x1, 15); x1 ^= x0;
    x0 += x1; x1 = tf_rotl(x1, 26); x1 ^= x0;
    x0 += x1; x1 = tf_rotl(x1,  6); x1 ^= x0;
    x0 += k1; x1 += ks2 + 1u;
    x0 += x1; x1 = tf_rotl(x1, 17); x1 ^= x0;
    x0 += x1; x1 = tf_rotl(x1, 29); x1 ^= x0;
    x0 += x1; x1 = tf_rotl(x1, 16); x1 ^= x0;
    x0 += x1; x1 = tf_rotl(x1, 24); x1 ^= x0;
    x0 += ks2; x1 += k0 + 2u;
    x0 += x1; x1 = tf_rotl(x1, 13); x1 ^= x0;
    x0 += x1; x1 = tf_rotl(x1, 15); x1 ^= x0;
    x0 += x1; x1 = tf_rotl(x1, 26); x1 ^= x0;
    x0 += x1; x1 = tf_rotl(x1,  6); x1 ^= x0;
    x0 += k0; x1 += k1 + 3u;
    x0 += x1; x1 = tf_rotl(x1, 17); x1 ^= x0;
    x0 += x1; x1 = tf_rotl(x1, 29); x1 ^= x0;
    x0 += x1; x1 = tf_rotl(x1, 16); x1 ^= x0;
    x0 += x1; x1 = tf_rotl(x1, 24); x1 ^= x0;
    x0 += k1; x1 += ks2 + 4u;
    x0 += x1; x1 = tf_rotl(x1, 13); x1 ^= x0;
    x0 += x1; x1 = tf_rotl(x1, 15); x1 ^= x0;
    x0 += x1; x1 = tf_rotl(x1, 26); x1 ^= x0;
    x0 += x1; x1 = tf_rotl(x1,  6); x1 ^= x0;
    x0 += ks2; x1 += k0 + 5u;
    o0 = x0; o1 = x1;
}

// ---------------------------------------------------------------------------
// Pack / maskall / prep / unpack
// ---------------------------------------------------------------------------
__global__ void nca_pack_kernel(const float* __restrict__ x)
{
    int p = blockIdx.x * 256 + threadIdx.x;
    if (blockIdx.x == 0 && threadIdx.x < STEPS) {
        g_cnt[threadIdx.x] = 0; g_icnt[threadIdx.x] = 0;
    }
    if (p >= NPIX) return;
    int b = p >> 16, hw = p & 65535;
    float v[CCH];
#pragma unroll
    for (int c = 0; c < CCH; ++c)
        v[c] = x[((size_t)(b * CCH + c) << 16) + hw];
    float4* dst = reinterpret_cast<float4*>(g_state[0] + ((size_t)p << 4));
    dst[0] = make_float4(v[0], v[1], v[2], v[3]);
    dst[1] = make_float4(v[4], v[5], v[6], v[7]);
    dst[2] = make_float4(v[8], v[9], v[10], v[11]);
    dst[3] = make_float4(v[12], v[13], v[14], v[15]);
}

__global__ void nca_maskall_kernel(KeyArr keys)
{
    int p = blockIdx.x * 256 + threadIdx.x;
    const int lane = threadIdx.x & 31;
#pragma unroll 1
    for (int s = 0; s < STEPS; ++s) {
        uint32_t r0, r1;
        threefry2x32(keys.k0[s], keys.k1[s], 0u, (uint32_t)p, r0, r1);
        uint32_t bits = r0 ^ r1;
        float u = __uint_as_float((bits >> 9) | 0x3f800000u) - 1.0f;
        bool active = (u <= 0.5f);
        unsigned ball = __ballot_sync(0xffffffffu, active);
        int nact = __popc(ball);
        int rank = __popc(ball & ((1u << lane) - 1u));
        int baseA = 0, baseI = 0;
        if (lane == 0) {
            if (nact > 0)  baseA = atomicAdd(&g_cnt[s], nact);
            if (nact < 32) baseI = atomicAdd(&g_icnt[s], 32 - nact);
        }
        baseA = __shfl_sync(0xffffffffu, baseA, 0);
        baseI = __shfl_sync(0xffffffffu, baseI, 0);
        if (active) g_list[s][baseA + rank] = p;
        else        g_ilist[s][baseI + (lane - rank)] = p;
    }
}

__global__ void nca_prep_kernel(const float* __restrict__ w_fc0)
{
    int i = blockIdx.x * 256 + threadIdx.x;
    if (i < HID * 48) {
        int n = i / 48, k = i % 48;
        uint32_t hi, lo; split_tf32(w_fc0[k * HID + n], hi, lo);
        g_w0t_hi[i] = __uint_as_float(hi);
        g_w0t_lo[i] = __uint_as_float(lo);
    }
}

__global__ void nca_unpack_kernel(float* __restrict__ out)
{
    int p = blockIdx.x * 256 + threadIdx.x;
    if (p >= NPIX) return;
    int b = p >> 16, hw = p & 65535;
    const float4* src = reinterpret_cast<const float4*>(g_state[0] + ((size_t)p << 4));
    float4 a0 = src[0], a1 = src[1], a2 = src[2], a3 = src[3];
    float v[CCH] = {a0.x,a0.y,a0.z,a0.w, a1.x,a1.y,a1.z,a1.w,
                    a2.x,a2.y,a2.z,a2.w, a3.x,a3.y,a3.z,a3.w};
    out[((size_t)b << 16) + hw] = v[3];
    float* xf = out + NPIX;
#pragma unroll
    for (int c = 0; c < CCH; ++c)
        xf[((size_t)(b * CCH + c) << 16) + hw] = v[c];
}

// ---------------------------------------------------------------------------
// SMEM layout (float offsets)
// ---------------------------------------------------------------------------
#define AP 52      // A/B row pad (48 data floats)
#define W1P 20
#define SM_BIAS 0                       // 128
#define SM_P0   128                     // 144
#define SM_P1   272                     // 144
#define SM_W1   416                     // 128*20 = 2560
#define SM_BH   (SM_W1 + 2560)          // 128*52 = 6656
#define SM_BL   (SM_BH + 6656)          // 6656
#define SM_AH   (SM_BL + 6656)          // 256*52 = 13312
#define SM_AL   (SM_AH + 13312)         // 13312
#define SM_DX   (SM_AL + 13312)         // 256*20 = 5120
#define SM_FLOATS (SM_DX + 5120)
#define SM_BYTES  (SM_FLOATS * 4)

// ---------------------------------------------------------------------------
// Step kernel: persistent 148 blocks x 256 threads; 256-px tiles.
// I/O phases quad-distributed: 4 lanes own one pixel (lane sub -> 16B chunk).
// ---------------------------------------------------------------------------
__global__ void __launch_bounds__(256, 1)
nca_step_mma(int src, int step,
             const float* __restrict__ w_p0, const float* __restrict__ w_p1,
             const float* __restrict__ b_fc0, const float* __restrict__ w_fc1)
{
    extern __shared__ float sm[];
    float* s_bias = sm + SM_BIAS;
    float* s_p0   = sm + SM_P0;
    float* s_p1   = sm + SM_P1;
    float* s_W1   = sm + SM_W1;
    float* s_BH   = sm + SM_BH;
    float* s_BL   = sm + SM_BL;
    float* s_AH   = sm + SM_AH;
    float* s_AL   = sm + SM_AL;
    float* s_DX   = sm + SM_DX;

    const float* cur = g_state[src];
    float*       nxt = g_state[src ^ 1];
    const int tid  = threadIdx.x;
    const int lane = tid & 31;
    const int g  = lane >> 2;
    const int tg = lane & 3;
    const int R  = (tid >> 5) * 32;   // warp's GEMM row base
    const int Q   = tid >> 2;         // quad index (0..63)
    const int sub = tid & 3;          // channel-chunk owner (0..3)

    // ---- stage constants once ----
    if (tid < 128) s_bias[tid] = b_fc0[tid];
    if (tid < 144) { s_p0[tid] = w_p0[tid]; s_p1[tid] = w_p1[tid]; }
    for (int i = tid; i < HID * CCH; i += 256)
        s_W1[(i >> 4) * W1P + (i & 15)] = w_fc1[i];
    for (int i = tid; i < HID * 48; i += 256) {
        int n = i / 48, k = i % 48;
        s_BH[n * AP + k] = g_w0t_hi[i];
        s_BL[n * AP + k] = g_w0t_lo[i];
    }
    __syncthreads();

    const int count = g_cnt[step];
    const int* al = g_list[step];
    const int ntiles = (count + 255) >> 8;

#pragma unroll 1
    for (int tile = blockIdx.x; tile < ntiles; tile += NSM_BLOCKS) {

        // =========== phase 1: perception + A staging (quad-mapped) ===========
        float cenr[4][4];
        int   pxr[4];
#pragma unroll 1
        for (int r = 0; r < 4; ++r) {
            const int li  = tile * 256 + r * 64 + Q;
            const int row = r * 64 + Q;
            const int p   = al[(li < count) ? li : (count - 1)];
            pxr[r] = (li < count) ? p : -1;
            const float* base = cur + ((size_t)(p >> 16) << 20);
            const int h = (p >> 8) & 255, w = p & 255;

            u64 c0a = 0ull, c0b = 0ull, c1a = 0ull, c1b = 0ull;
            u64 cen0 = 0ull, cen1 = 0ull;
#pragma unroll
            for (int dh = -1; dh <= 1; ++dh) {
                int hh = h + dh; hh = (hh < 0) ? 1 : ((hh > 255) ? 254 : hh);
#pragma unroll
                for (int dw = -1; dw <= 1; ++dw) {
                    int ww = w + dw; ww = (ww < 0) ? 1 : ((ww > 255) ? 254 : ww);
                    const ulonglong2 v = *reinterpret_cast<const ulonglong2*>(
                        base + (((size_t)((hh << 8) | ww)) << 4) + sub * 4);
                    const int tap = (dh + 1) * 3 + (dw + 1);
                    const ulonglong2 t0 = *reinterpret_cast<const ulonglong2*>(
                        s_p0 + tap * 16 + sub * 4);
                    const ulonglong2 t1 = *reinterpret_cast<const ulonglong2*>(
                        s_p1 + tap * 16 + sub * 4);
                    ffma2(c0a, v.x, t0.x); ffma2(c0b, v.y, t0.y);
                    ffma2(c1a, v.x, t1.x); ffma2(c1b, v.y, t1.y);
                    if (dh == 0 && dw == 0) { cen0 = v.x; cen1 = v.y; }
                }
            }
            float2 f0 = unpack2(cen0), f1 = unpack2(cen1);
            float2 a0 = unpack2(c0a),  a1 = unpack2(c0b);
            float2 b0 = unpack2(c1a),  b1 = unpack2(c1b);
            cenr[r][0] = f0.x; cenr[r][1] = f0.y; cenr[r][2] = f1.x; cenr[r][3] = f1.y;

            const float vals[12] = {f0.x, f0.y, f1.x, f1.y,
                                    a0.x, a0.y, a1.x, a1.y,
                                    b0.x, b0.y, b1.x, b1.y};
            uint32_t hi[12], lo[12];
#pragma unroll
            for (int j = 0; j < 12; ++j) split_tf32(vals[j], hi[j], lo[j]);
            float* ah = s_AH + row * AP + sub * 4;
            float* alp = s_AL + row * AP + sub * 4;
#pragma unroll
            for (int c3 = 0; c3 < 3; ++c3) {
                *reinterpret_cast<float4*>(ah + c3 * 16) = make_float4(
                    __uint_as_float(hi[4*c3]),   __uint_as_float(hi[4*c3+1]),
                    __uint_as_float(hi[4*c3+2]), __uint_as_float(hi[4*c3+3]));
                *reinterpret_cast<float4*>(alp + c3 * 16) = make_float4(
                    __uint_as_float(lo[4*c3]),   __uint_as_float(lo[4*c3+1]),
                    __uint_as_float(lo[4*c3+2]), __uint_as_float(lo[4*c3+3]));
            }
        }
        __syncthreads();

        // =========== phase 2: GEMM1 (mma tf32 x3) + epilogue + GEMM2 =========
        u64 dx2[2][2][8];
#pragma unroll
        for (int m = 0; m < 2; ++m)
#pragma unroll
            for (int r = 0; r < 2; ++r)
#pragma unroll
                for (int j = 0; j < 8; ++j) dx2[m][r][j] = 0ull;

#pragma unroll 1
        for (int nh = 0; nh < 2; ++nh) {
            float acc[2][8][4];
#pragma unroll
            for (int m = 0; m < 2; ++m)
#pragma unroll
                for (int nt = 0; nt < 8; ++nt)
#pragma unroll
                    for (int j = 0; j < 4; ++j) acc[m][nt][j] = 0.0f;

#pragma unroll 1
            for (int kt = 0; kt < 6; ++kt) {
                const int kc = kt * 8 + tg;
                uint32_t ah[2][4], alr[2][4];
#pragma unroll
                for (int m = 0; m < 2; ++m) {
                    const int r0 = R + m * 16 + g;
                    ah[m][0]  = __float_as_uint(s_AH[r0 * AP + kc]);
                    ah[m][1]  = __float_as_uint(s_AH[(r0 + 8) * AP + kc]);
                    ah[m][2]  = __float_as_uint(s_AH[r0 * AP + kc + 4]);
                    ah[m][3]  = __float_as_uint(s_AH[(r0 + 8) * AP + kc + 4]);
                    alr[m][0] = __float_as_uint(s_AL[r0 * AP + kc]);
                    alr[m][1] = __float_as_uint(s_AL[(r0 + 8) * AP + kc]);
                    alr[m][2] = __float_as_uint(s_AL[r0 * AP + kc + 4]);
                    alr[m][3] = __float_as_uint(s_AL[(r0 + 8) * AP + kc + 4]);
                }
#pragma unroll
                for (int nt = 0; nt < 8; ++nt) {
                    const int n = (nh * 8 + nt) * 8 + g;
                    uint32_t bh0 = __float_as_uint(s_BH[n * AP + kc]);
                    uint32_t bh1 = __float_as_uint(s_BH[n * AP + kc + 4]);
                    uint32_t bl0 = __float_as_uint(s_BL[n * AP + kc]);
                    uint32_t bl1 = __float_as_uint(s_BL[n * AP + kc + 4]);
#pragma unroll
                    for (int m = 0; m < 2; ++m) {
                        mma_tf32(acc[m][nt], ah[m],  bh0, bh1);
                        mma_tf32(acc[m][nt], ah[m],  bl0, bl1);
                        mma_tf32(acc[m][nt], alr[m], bh0, bh1);
                    }
                }
            }

#pragma unroll
            for (int nt = 0; nt < 8; ++nt) {
                const int t0 = nh * 64 + nt * 8 + 2 * tg;
                const float bf0 = s_bias[t0], bf1 = s_bias[t0 + 1];
                u64 wa[8], wb[8];
                {
                    const ulonglong2* w1a = reinterpret_cast<const ulonglong2*>(s_W1 + t0 * W1P);
                    const ulonglong2* w1b = reinterpret_cast<const ulonglong2*>(s_W1 + (t0 + 1) * W1P);
#pragma unroll
                    for (int q = 0; q < 4; ++q) {
                        ulonglong2 ta = w1a[q], tb = w1b[q];
                        wa[2*q] = ta.x; wa[2*q+1] = ta.y;
                        wb[2*q] = tb.x; wb[2*q+1] = tb.y;
                    }
                }
#pragma unroll
                for (int m = 0; m < 2; ++m) {
                    u64 H00 = pack2dup(fmaxf(acc[m][nt][0] + bf0, 0.0f));
                    u64 H01 = pack2dup(fmaxf(acc[m][nt][1] + bf1, 0.0f));
                    u64 H10 = pack2dup(fmaxf(acc[m][nt][2] + bf0, 0.0f));
                    u64 H11 = pack2dup(fmaxf(acc[m][nt][3] + bf1, 0.0f));
#pragma unroll
                    for (int j = 0; j < 8; ++j) {
                        ffma2(dx2[m][0][j], H00, wa[j]);
                        ffma2(dx2[m][0][j], H01, wb[j]);
                        ffma2(dx2[m][1][j], H10, wa[j]);
                        ffma2(dx2[m][1][j], H11, wb[j]);
                    }
                }
            }
        }

        // quad reduce + stage dx
#pragma unroll
        for (int m = 0; m < 2; ++m) {
#pragma unroll
            for (int r = 0; r < 2; ++r) {
                float red[16];
#pragma unroll
                for (int j = 0; j < 8; ++j) {
                    float2 f = unpack2(dx2[m][r][j]);
                    red[2*j] = f.x; red[2*j+1] = f.y;
                }
#pragma unroll
                for (int o = 0; o < 16; ++o) {
                    red[o] += __shfl_xor_sync(0xffffffffu, red[o], 1);
                    red[o] += __shfl_xor_sync(0xffffffffu, red[o], 2);
                }
                if (tg == 0) {
                    const int row = R + m * 16 + r * 8 + g;
                    float* d = s_DX + row * W1P;
                    *reinterpret_cast<float4*>(d +  0) = make_float4(red[0],  red[1],  red[2],  red[3]);
                    *reinterpret_cast<float4*>(d +  4) = make_float4(red[4],  red[5],  red[6],  red[7]);
                    *reinterpret_cast<float4*>(d +  8) = make_float4(red[8],  red[9],  red[10], red[11]);
                    *reinterpret_cast<float4*>(d + 12) = make_float4(red[12], red[13], red[14], red[15]);
                }
            }
        }
        __syncthreads();

        // =========== phase 3: residual update + store (quad-mapped) ==========
#pragma unroll
        for (int r = 0; r < 4; ++r) {
            if (pxr[r] < 0) continue;
            const int row = r * 64 + Q;
            float4 dx = *reinterpret_cast<float4*>(s_DX + row * W1P + sub * 4);
            float o0 = cenr[r][0] + dx.x;
            float o1 = cenr[r][1] + dx.y;
            float o2 = cenr[r][2] + dx.z;
            float o3 = cenr[r][3] + dx.w;
            if (sub == 0) { o0 = cenr[r][0]; o1 = cenr[r][1]; o2 = cenr[r][2]; }
            *reinterpret_cast<float4*>(nxt + ((size_t)pxr[r] << 4) + sub * 4) =
                make_float4(o0, o1, o2, o3);
        }
        __syncthreads();
    }

    // ---- inactive copy-through (quad-mapped: 16B per lane, full coverage) ----
    const int icnt = g_icnt[step];
    const int* il = g_ilist[step];
    const int itot = icnt * 4;
    for (int j = blockIdx.x * 256 + tid; j < itot; j += NSM_BLOCKS * 256) {
        int idx = j >> 2, s2 = j & 3;
        int p = il[idx];
        const float4 v = *reinterpret_cast<const float4*>(
            cur + ((size_t)p << 4) + s2 * 4);
        *reinterpret_cast<float4*>(nxt + ((size_t)p << 4) + s2 * 4) = v;
    }
}

// ---------------------------------------------------------------------------
// Launch
// ---------------------------------------------------------------------------
extern "C" void kernel_launch(void* const* d_in, const int* in_sizes, int n_in,
                              void* d_out, int out_size)
{
    const float* x      = (const float*)d_in[0];
    const float* w_p0   = (const float*)d_in[1];
    const float* w_p1   = (const float*)d_in[2];
    const float* w_fc0  = (const float*)d_in[3];
    const float* b_fc0  = (const float*)d_in[4];
    const float* w_fc1  = (const float*)d_in[5];
    float* out = (float*)d_out;

    KeyArr keys;
    for (int j = 0; j < STEPS; ++j) {
        uint32_t a, b;
        threefry2x32(0u, 42u, 0u, (uint32_t)j, a, b);
        keys.k0[j] = a; keys.k1[j] = b;
    }

    cudaFuncSetAttribute(nca_step_mma,
                         cudaFuncAttributeMaxDynamicSharedMemorySize, SM_BYTES);

    nca_pack_kernel<<<NPIX / 256, 256>>>(x);
    nca_maskall_kernel<<<NPIX / 256, 256>>>(keys);
    nca_prep_kernel<<<(HID * 48 + 255) / 256, 256>>>(w_fc0);
    for (int s = 0; s < STEPS; ++s) {
        nca_step_mma<<<NSM_BLOCKS, 256, SM_BYTES>>>(
            s & 1, s, w_p0, w_p1, b_fc0, w_fc1);
    }
    nca_unpack_kernel<<<NPIX / 256, 256>>>(out);
}

// round 13
// speedup vs baseline: 1.0239x; 1.0239x over previous
#include <cuda_runtime.h>
#include <cstdint>

// ---------------------------------------------------------------------------
// Problem constants
// ---------------------------------------------------------------------------
#define BATCH 8
#define IMG   256
#define CCH   16
#define HID   128
#define NPIX  (BATCH * IMG * IMG)
#define STATE_ELEMS (NPIX * CCH)
#define STEPS 32
#define LIST_CAP (NPIX / 2 + 8192)
#define NSM_BLOCKS 148
#define NTHREADS 512

typedef unsigned long long u64;

__device__ float g_state[2][STATE_ELEMS];
__device__ int g_list[STEPS][LIST_CAP];
__device__ int g_ilist[STEPS][LIST_CAP];
__device__ int g_cnt[STEPS];
__device__ int g_icnt[STEPS];
// W0^T split into tf32 hi/lo: [n=128][k=48]
__device__ float g_w0t_hi[HID * 48];
__device__ float g_w0t_lo[HID * 48];

struct KeyArr { uint32_t k0[STEPS]; uint32_t k1[STEPS]; };

// ---------------------------------------------------------------------------
// packed f32x2 helpers (bit-exact: two independent rn fp32 FMAs)
// ---------------------------------------------------------------------------
static __device__ __forceinline__ u64 pack2dup(float x) {
    u64 r; asm("mov.b64 %0, {%1, %1};" : "=l"(r) : "f"(x)); return r;
}
static __device__ __forceinline__ void ffma2(u64& acc, u64 a, u64 b) {
    asm("fma.rn.f32x2 %0, %1, %2, %0;" : "+l"(acc) : "l"(a), "l"(b));
}
static __device__ __forceinline__ float2 unpack2(u64 v) {
    float2 f; asm("mov.b64 {%0, %1}, %2;" : "=f"(f.x), "=f"(f.y) : "l"(v)); return f;
}

// ---------------------------------------------------------------------------
// tf32 split
// ---------------------------------------------------------------------------
static __device__ __forceinline__ uint32_t cvt_tf32(float v) {
    uint32_t r; asm("cvt.rna.tf32.f32 %0, %1;" : "=r"(r) : "f"(v)); return r;
}
static __device__ __forceinline__ void split_tf32(float v, uint32_t& hi, uint32_t& lo) {
    hi = cvt_tf32(v);
    lo = cvt_tf32(v - __uint_as_float(hi));
}

// ---------------------------------------------------------------------------
// warp mma: m16n8k8 tf32 (sm_80 baseline PTX — legal on sm_103)
// ---------------------------------------------------------------------------
static __device__ __forceinline__ void mma_tf32(
    float* d, const uint32_t* a, uint32_t b0, uint32_t b1)
{
    asm volatile(
        "mma.sync.aligned.m16n8k8.row.col.f32.tf32.tf32.f32 "
        "{%0,%1,%2,%3},{%4,%5,%6,%7},{%8,%9},{%0,%1,%2,%3};"
        : "+f"(d[0]), "+f"(d[1]), "+f"(d[2]), "+f"(d[3])
        : "r"(a[0]), "r"(a[1]), "r"(a[2]), "r"(a[3]), "r"(b0), "r"(b1));
}

// ---------------------------------------------------------------------------
// Threefry-2x32 — exact JAX
// ---------------------------------------------------------------------------
static __host__ __device__ __forceinline__ uint32_t tf_rotl(uint32_t v, int r) {
    return (v << r) | (v >> (32 - r));
}
static __host__ __device__ __forceinline__ void threefry2x32(
    uint32_t k0, uint32_t k1, uint32_t x0, uint32_t x1,
    uint32_t& o0, uint32_t& o1)
{
    uint32_t ks2 = k0 ^ k1 ^ 0x1BD11BDAu;
    x0 += k0; x1 += k1;
    x0 += x1; x1 = tf_rotl(x1, 13); x1 ^= x0;
    x0 += x1; x1 = tf_rotl(x1, 15); x1 ^= x0;
    x0 += x1; x1 = tf_rotl(x1, 26); x1 ^= x0;
    x0 += x1; x1 = tf_rotl(x1,  6); x1 ^= x0;
    x0 += k1; x1 += ks2 + 1u;
    x0 += x1; x1 = tf_rotl(x1, 17); x1 ^= x0;
    x0 += x1; x1 = tf_rotl(x1, 29); x1 ^= x0;
    x0 += x1; x1 = tf_rotl(x1, 16); x1 ^= x0;
    x0 += x1; x1 = tf_rotl(x1, 24); x1 ^= x0;
    x0 += ks2; x1 += k0 + 2u;
    x0 += x1; x1 = tf_rotl(x1, 13); x1 ^= x0;
    x0 += x1; x1 = tf_rotl(x1, 15); x1 ^= x0;
    x0 += x1; x1 = tf_rotl(x1, 26); x1 ^= x0;
    x0 += x1; x1 = tf_rotl(x1,  6); x1 ^= x0;
    x0 += k0; x1 += k1 + 3u;
    x0 += x1; x1 = tf_rotl(x1, 17); x1 ^= x0;
    x0 += x1; x1 = tf_rotl(x1, 29); x1 ^= x0;
    x0 += x1; x1 = tf_rotl(x1, 16); x1 ^= x0;
    x0 += x1; x1 = tf_rotl(x1, 24); x1 ^= x0;
    x0 += k1; x1 += ks2 + 4u;
    x0 += x1; x1 = tf_rotl(x1, 13); x1 ^= x0;
    x0 += x1; x1 = tf_rotl(x1, 15); x1 ^= x0;
    x0 += x1; x1 = tf_rotl(x1, 26); x1 ^= x0;
    x0 += x1; x1 = tf_rotl(x1,  6); x1 ^= x0;
    x0 += ks2; x1 += k0 + 5u;
    o0 = x0; o1 = x1;
}

// ---------------------------------------------------------------------------
// Pack / maskall / prep / unpack
// ---------------------------------------------------------------------------
__global__ void nca_pack_kernel(const float* __restrict__ x)
{
    int p = blockIdx.x * 256 + threadIdx.x;
    if (blockIdx.x == 0 && threadIdx.x < STEPS) {
        g_cnt[threadIdx.x] = 0; g_icnt[threadIdx.x] = 0;
    }
    if (p >= NPIX) return;
    int b = p >> 16, hw = p & 65535;
    float v[CCH];
#pragma unroll
    for (int c = 0; c < CCH; ++c)
        v[c] = x[((size_t)(b * CCH + c) << 16) + hw];
    float4* dst = reinterpret_cast<float4*>(g_state[0] + ((size_t)p << 4));
    dst[0] = make_float4(v[0], v[1], v[2], v[3]);
    dst[1] = make_float4(v[4], v[5], v[6], v[7]);
    dst[2] = make_float4(v[8], v[9], v[10], v[11]);
    dst[3] = make_float4(v[12], v[13], v[14], v[15]);
}

__global__ void nca_maskall_kernel(KeyArr keys)
{
    int p = blockIdx.x * 256 + threadIdx.x;
    const int lane = threadIdx.x & 31;
#pragma unroll 1
    for (int s = 0; s < STEPS; ++s) {
        uint32_t r0, r1;
        threefry2x32(keys.k0[s], keys.k1[s], 0u, (uint32_t)p, r0, r1);
        uint32_t bits = r0 ^ r1;
        float u = __uint_as_float((bits >> 9) | 0x3f800000u) - 1.0f;
        bool active = (u <= 0.5f);
        unsigned ball = __ballot_sync(0xffffffffu, active);
        int nact = __popc(ball);
        int rank = __popc(ball & ((1u << lane) - 1u));
        int baseA = 0, baseI = 0;
        if (lane == 0) {
            if (nact > 0)  baseA = atomicAdd(&g_cnt[s], nact);
            if (nact < 32) baseI = atomicAdd(&g_icnt[s], 32 - nact);
        }
        baseA = __shfl_sync(0xffffffffu, baseA, 0);
        baseI = __shfl_sync(0xffffffffu, baseI, 0);
        if (active) g_list[s][baseA + rank] = p;
        else        g_ilist[s][baseI + (lane - rank)] = p;
    }
}

__global__ void nca_prep_kernel(const float* __restrict__ w_fc0)
{
    int i = blockIdx.x * 256 + threadIdx.x;
    if (i < HID * 48) {
        int n = i / 48, k = i % 48;
        uint32_t hi, lo; split_tf32(w_fc0[k * HID + n], hi, lo);
        g_w0t_hi[i] = __uint_as_float(hi);
        g_w0t_lo[i] = __uint_as_float(lo);
    }
}

__global__ void nca_unpack_kernel(float* __restrict__ out)
{
    int p = blockIdx.x * 256 + threadIdx.x;
    if (p >= NPIX) return;
    int b = p >> 16, hw = p & 65535;
    const float4* src = reinterpret_cast<const float4*>(g_state[0] + ((size_t)p << 4));
    float4 a0 = src[0], a1 = src[1], a2 = src[2], a3 = src[3];
    float v[CCH] = {a0.x,a0.y,a0.z,a0.w, a1.x,a1.y,a1.z,a1.w,
                    a2.x,a2.y,a2.z,a2.w, a3.x,a3.y,a3.z,a3.w};
    out[((size_t)b << 16) + hw] = v[3];
    float* xf = out + NPIX;
#pragma unroll
    for (int c = 0; c < CCH; ++c)
        xf[((size_t)(b * CCH + c) << 16) + hw] = v[c];
}

// ---------------------------------------------------------------------------
// SMEM layout (float offsets)
// ---------------------------------------------------------------------------
#define AP 52      // A/B row pad (48 data floats)
#define W1P 20
#define SM_BIAS 0                       // 128
#define SM_P0   128                     // 144
#define SM_P1   272                     // 144
#define SM_W1   416                     // 128*20 = 2560
#define SM_BH   (SM_W1 + 2560)          // 128*52 = 6656
#define SM_BL   (SM_BH + 6656)          // 6656
#define SM_AH   (SM_BL + 6656)          // 256*52 = 13312
#define SM_AL   (SM_AH + 13312)         // 13312
#define SM_DX   (SM_AL + 13312)         // 256*20 = 5120
#define SM_FLOATS (SM_DX + 5120)
#define SM_BYTES  (SM_FLOATS * 4)

// ---------------------------------------------------------------------------
// Step kernel: persistent 148 blocks x 512 threads (16 warps/SM); 256-px tiles.
// Phase 1/3 quad-mapped (2 rows/thread); phase 2: 16 warps x M=16 rows.
// ---------------------------------------------------------------------------
__global__ void __launch_bounds__(NTHREADS, 1)
nca_step_mma(int src, int step,
             const float* __restrict__ w_p0, const float* __restrict__ w_p1,
             const float* __restrict__ b_fc0, const float* __restrict__ w_fc1)
{
    extern __shared__ float sm[];
    float* s_bias = sm + SM_BIAS;
    float* s_p0   = sm + SM_P0;
    float* s_p1   = sm + SM_P1;
    float* s_W1   = sm + SM_W1;
    float* s_BH   = sm + SM_BH;
    float* s_BL   = sm + SM_BL;
    float* s_AH   = sm + SM_AH;
    float* s_AL   = sm + SM_AL;
    float* s_DX   = sm + SM_DX;

    const float* cur = g_state[src];
    float*       nxt = g_state[src ^ 1];
    const int tid  = threadIdx.x;
    const int lane = tid & 31;
    const int g  = lane >> 2;
    const int tg = lane & 3;
    const int R  = (tid >> 5) * 16;   // warp's GEMM row base (16 warps x 16 rows)
    const int Q   = tid >> 2;         // quad index (0..127)
    const int sub = tid & 3;          // channel-chunk owner (0..3)

    // ---- stage constants once ----
    if (tid < 128) s_bias[tid] = b_fc0[tid];
    if (tid < 144) { s_p0[tid] = w_p0[tid]; s_p1[tid] = w_p1[tid]; }
    for (int i = tid; i < HID * CCH; i += NTHREADS)
        s_W1[(i >> 4) * W1P + (i & 15)] = w_fc1[i];
    for (int i = tid; i < HID * 48; i += NTHREADS) {
        int n = i / 48, k = i % 48;
        s_BH[n * AP + k] = g_w0t_hi[i];
        s_BL[n * AP + k] = g_w0t_lo[i];
    }
    __syncthreads();

    const int count = g_cnt[step];
    const int* al = g_list[step];
    const int ntiles = (count + 255) >> 8;

#pragma unroll 1
    for (int tile = blockIdx.x; tile < ntiles; tile += NSM_BLOCKS) {

        // =========== phase 1: perception + A staging (quad-mapped, 2 rows) ===
        float cenr[2][4];
        int   pxr[2];
#pragma unroll 1
        for (int r = 0; r < 2; ++r) {
            const int row = r * 128 + Q;
            const int li  = tile * 256 + row;
            const int p   = al[(li < count) ? li : (count - 1)];
            pxr[r] = (li < count) ? p : -1;
            const float* base = cur + ((size_t)(p >> 16) << 20);
            const int h = (p >> 8) & 255, w = p & 255;

            u64 c0a = 0ull, c0b = 0ull, c1a = 0ull, c1b = 0ull;
            u64 cen0 = 0ull, cen1 = 0ull;
#pragma unroll
            for (int dh = -1; dh <= 1; ++dh) {
                int hh = h + dh; hh = (hh < 0) ? 1 : ((hh > 255) ? 254 : hh);
#pragma unroll
                for (int dw = -1; dw <= 1; ++dw) {
                    int ww = w + dw; ww = (ww < 0) ? 1 : ((ww > 255) ? 254 : ww);
                    const ulonglong2 v = *reinterpret_cast<const ulonglong2*>(
                        base + (((size_t)((hh << 8) | ww)) << 4) + sub * 4);
                    const int tap = (dh + 1) * 3 + (dw + 1);
                    const ulonglong2 t0 = *reinterpret_cast<const ulonglong2*>(
                        s_p0 + tap * 16 + sub * 4);
                    const ulonglong2 t1 = *reinterpret_cast<const ulonglong2*>(
                        s_p1 + tap * 16 + sub * 4);
                    ffma2(c0a, v.x, t0.x); ffma2(c0b, v.y, t0.y);
                    ffma2(c1a, v.x, t1.x); ffma2(c1b, v.y, t1.y);
                    if (dh == 0 && dw == 0) { cen0 = v.x; cen1 = v.y; }
                }
            }
            float2 f0 = unpack2(cen0), f1 = unpack2(cen1);
            float2 a0 = unpack2(c0a),  a1 = unpack2(c0b);
            float2 b0 = unpack2(c1a),  b1 = unpack2(c1b);
            cenr[r][0] = f0.x; cenr[r][1] = f0.y; cenr[r][2] = f1.x; cenr[r][3] = f1.y;

            const float vals[12] = {f0.x, f0.y, f1.x, f1.y,
                                    a0.x, a0.y, a1.x, a1.y,
                                    b0.x, b0.y, b1.x, b1.y};
            uint32_t hi[12], lo[12];
#pragma unroll
            for (int j = 0; j < 12; ++j) split_tf32(vals[j], hi[j], lo[j]);
            float* ah = s_AH + row * AP + sub * 4;
            float* alp = s_AL + row * AP + sub * 4;
#pragma unroll
            for (int c3 = 0; c3 < 3; ++c3) {
                *reinterpret_cast<float4*>(ah + c3 * 16) = make_float4(
                    __uint_as_float(hi[4*c3]),   __uint_as_float(hi[4*c3+1]),
                    __uint_as_float(hi[4*c3+2]), __uint_as_float(hi[4*c3+3]));
                *reinterpret_cast<float4*>(alp + c3 * 16) = make_float4(
                    __uint_as_float(lo[4*c3]),   __uint_as_float(lo[4*c3+1]),
                    __uint_as_float(lo[4*c3+2]), __uint_as_float(lo[4*c3+3]));
            }
        }
        __syncthreads();

        // =========== phase 2: GEMM1 (mma tf32 x3) + epilogue + GEMM2 =========
        u64 dx2[2][8];
#pragma unroll
        for (int r = 0; r < 2; ++r)
#pragma unroll
            for (int j = 0; j < 8; ++j) dx2[r][j] = 0ull;

#pragma unroll 1
        for (int nh = 0; nh < 2; ++nh) {
            float acc[8][4];
#pragma unroll
            for (int nt = 0; nt < 8; ++nt)
#pragma unroll
                for (int j = 0; j < 4; ++j) acc[nt][j] = 0.0f;

#pragma unroll 1
            for (int kt = 0; kt < 6; ++kt) {
                const int kc = kt * 8 + tg;
                const int r0 = R + g;
                uint32_t ah[4], alr[4];
                ah[0]  = __float_as_uint(s_AH[r0 * AP + kc]);
                ah[1]  = __float_as_uint(s_AH[(r0 + 8) * AP + kc]);
                ah[2]  = __float_as_uint(s_AH[r0 * AP + kc + 4]);
                ah[3]  = __float_as_uint(s_AH[(r0 + 8) * AP + kc + 4]);
                alr[0] = __float_as_uint(s_AL[r0 * AP + kc]);
                alr[1] = __float_as_uint(s_AL[(r0 + 8) * AP + kc]);
                alr[2] = __float_as_uint(s_AL[r0 * AP + kc + 4]);
                alr[3] = __float_as_uint(s_AL[(r0 + 8) * AP + kc + 4]);
#pragma unroll
                for (int nt = 0; nt < 8; ++nt) {
                    const int n = (nh * 8 + nt) * 8 + g;
                    uint32_t bh0 = __float_as_uint(s_BH[n * AP + kc]);
                    uint32_t bh1 = __float_as_uint(s_BH[n * AP + kc + 4]);
                    uint32_t bl0 = __float_as_uint(s_BL[n * AP + kc]);
                    uint32_t bl1 = __float_as_uint(s_BL[n * AP + kc + 4]);
                    mma_tf32(acc[nt], ah,  bh0, bh1);
                    mma_tf32(acc[nt], ah,  bl0, bl1);
                    mma_tf32(acc[nt], alr, bh0, bh1);
                }
            }

            // epilogue: bias + relu; GEMM2 partial (packed FFMA2)
#pragma unroll
            for (int nt = 0; nt < 8; ++nt) {
                const int t0 = nh * 64 + nt * 8 + 2 * tg;
                const float bf0 = s_bias[t0], bf1 = s_bias[t0 + 1];
                u64 wa[8], wb[8];
                {
                    const ulonglong2* w1a = reinterpret_cast<const ulonglong2*>(s_W1 + t0 * W1P);
                    const ulonglong2* w1b = reinterpret_cast<const ulonglong2*>(s_W1 + (t0 + 1) * W1P);
#pragma unroll
                    for (int q = 0; q < 4; ++q) {
                        ulonglong2 ta = w1a[q], tb = w1b[q];
                        wa[2*q] = ta.x; wa[2*q+1] = ta.y;
                        wb[2*q] = tb.x; wb[2*q+1] = tb.y;
                    }
                }
                u64 H00 = pack2dup(fmaxf(acc[nt][0] + bf0, 0.0f));
                u64 H01 = pack2dup(fmaxf(acc[nt][1] + bf1, 0.0f));
                u64 H10 = pack2dup(fmaxf(acc[nt][2] + bf0, 0.0f));
                u64 H11 = pack2dup(fmaxf(acc[nt][3] + bf1, 0.0f));
#pragma unroll
                for (int j = 0; j < 8; ++j) {
                    ffma2(dx2[0][j], H00, wa[j]);
                    ffma2(dx2[0][j], H01, wb[j]);
                    ffma2(dx2[1][j], H10, wa[j]);
                    ffma2(dx2[1][j], H11, wb[j]);
                }
            }
        }

        // quad reduce + stage dx
#pragma unroll
        for (int r = 0; r < 2; ++r) {
            float red[16];
#pragma unroll
            for (int j = 0; j < 8; ++j) {
                float2 f = unpack2(dx2[r][j]);
                red[2*j] = f.x; red[2*j+1] = f.y;
            }
#pragma unroll
            for (int o = 0; o < 16; ++o) {
                red[o] += __shfl_xor_sync(0xffffffffu, red[o], 1);
                red[o] += __shfl_xor_sync(0xffffffffu, red[o], 2);
            }
            if (tg == 0) {
                const int row = R + r * 8 + g;
                float* d = s_DX + row * W1P;
                *reinterpret_cast<float4*>(d +  0) = make_float4(red[0],  red[1],  red[2],  red[3]);
                *reinterpret_cast<float4*>(d +  4) = make_float4(red[4],  red[5],  red[6],  red[7]);
                *reinterpret_cast<float4*>(d +  8) = make_float4(red[8],  red[9],  red[10], red[11]);
                *reinterpret_cast<float4*>(d + 12) = make_float4(red[12], red[13], red[14], red[15]);
            }
        }
        __syncthreads();

        // =========== phase 3: residual update + store (quad-mapped) ==========
#pragma unroll
        for (int r = 0; r < 2; ++r) {
            if (pxr[r] < 0) continue;
            const int row = r * 128 + Q;
            float4 dx = *reinterpret_cast<float4*>(s_DX + row * W1P + sub * 4);
            float o0 = cenr[r][0] + dx.x;
            float o1 = cenr[r][1] + dx.y;
            float o2 = cenr[r][2] + dx.z;
            float o3 = cenr[r][3] + dx.w;
            if (sub == 0) { o0 = cenr[r][0]; o1 = cenr[r][1]; o2 = cenr[r][2]; }
            *reinterpret_cast<float4*>(nxt + ((size_t)pxr[r] << 4) + sub * 4) =
                make_float4(o0, o1, o2, o3);
        }
        __syncthreads();
    }

    // ---- inactive copy-through (quad-mapped: 16B per lane, full coverage) ----
    const int icnt = g_icnt[step];
    const int* il = g_ilist[step];
    const int itot = icnt * 4;
    for (int j = blockIdx.x * NTHREADS + tid; j < itot; j += NSM_BLOCKS * NTHREADS) {
        int idx = j >> 2, s2 = j & 3;
        int p = il[idx];
        const float4 v = *reinterpret_cast<const float4*>(
            cur + ((size_t)p << 4) + s2 * 4);
        *reinterpret_cast<float4*>(nxt + ((size_t)p << 4) + s2 * 4) = v;
    }
}

// ---------------------------------------------------------------------------
// Launch
// ---------------------------------------------------------------------------
extern "C" void kernel_launch(void* const* d_in, const int* in_sizes, int n_in,
                              void* d_out, int out_size)
{
    const float* x      = (const float*)d_in[0];
    const float* w_p0   = (const float*)d_in[1];
    const float* w_p1   = (const float*)d_in[2];
    const float* w_fc0  = (const float*)d_in[3];
    const float* b_fc0  = (const float*)d_in[4];
    const float* w_fc1  = (const float*)d_in[5];
    float* out = (float*)d_out;

    KeyArr keys;
    for (int j = 0; j < STEPS; ++j) {
        uint32_t a, b;
        threefry2x32(0u, 42u, 0u, (uint32_t)j, a, b);
        keys.k0[j] = a; keys.k1[j] = b;
    }

    cudaFuncSetAttribute(nca_step_mma,
                         cudaFuncAttributeMaxDynamicSharedMemorySize, SM_BYTES);

    nca_pack_kernel<<<NPIX / 256, 256>>>(x);
    nca_maskall_kernel<<<NPIX / 256, 256>>>(keys);
    nca_prep_kernel<<<(HID * 48 + 255) / 256, 256>>>(w_fc0);
    for (int s = 0; s < STEPS; ++s) {
        nca_step_mma<<<NSM_BLOCKS, NTHREADS, SM_BYTES>>>(
            s & 1, s, w_p0, w_p1, b_fc0, w_fc1);
    }
    nca_unpack_kernel<<<NPIX / 256, 256>>>(out);
}

// round 14
// speedup vs baseline: 1.0858x; 1.0604x over previous
#include <cuda_runtime.h>
#include <cstdint>

// ---------------------------------------------------------------------------
// Problem constants
// ---------------------------------------------------------------------------
#define BATCH 8
#define IMG   256
#define CCH   16
#define HID   128
#define NPIX  (BATCH * IMG * IMG)
#define STATE_ELEMS (NPIX * CCH)
#define STEPS 32
#define LIST_CAP (NPIX / 2 + 8192)
#define NSM_BLOCKS 148

typedef unsigned long long u64;

__device__ float g_state[2][STATE_ELEMS];
__device__ int g_list[STEPS][LIST_CAP];
__device__ int g_ilist[STEPS][LIST_CAP];
__device__ int g_cnt[STEPS];
__device__ int g_icnt[STEPS];
// W0^T split into tf32 hi/lo: [n=128][k=48]
__device__ float g_w0t_hi[HID * 48];
__device__ float g_w0t_lo[HID * 48];

struct KeyArr { uint32_t k0[STEPS]; uint32_t k1[STEPS]; };

// ---------------------------------------------------------------------------
// packed f32x2 helpers (bit-exact: two independent rn fp32 FMAs)
// ---------------------------------------------------------------------------
static __device__ __forceinline__ u64 pack2dup(float x) {
    u64 r; asm("mov.b64 %0, {%1, %1};" : "=l"(r) : "f"(x)); return r;
}
static __device__ __forceinline__ void ffma2(u64& acc, u64 a, u64 b) {
    asm("fma.rn.f32x2 %0, %1, %2, %0;" : "+l"(acc) : "l"(a), "l"(b));
}
static __device__ __forceinline__ float2 unpack2(u64 v) {
    float2 f; asm("mov.b64 {%0, %1}, %2;" : "=f"(f.x), "=f"(f.y) : "l"(v)); return f;
}

// ---------------------------------------------------------------------------
// tf32 split
// ---------------------------------------------------------------------------
static __device__ __forceinline__ uint32_t cvt_tf32(float v) {
    uint32_t r; asm("cvt.rna.tf32.f32 %0, %1;" : "=r"(r) : "f"(v)); return r;
}
static __device__ __forceinline__ void split_tf32(float v, uint32_t& hi, uint32_t& lo) {
    hi = cvt_tf32(v);
    lo = cvt_tf32(v - __uint_as_float(hi));
}

// ---------------------------------------------------------------------------
// warp mma: m16n8k8 tf32 (sm_80 baseline PTX — legal on sm_103)
// ---------------------------------------------------------------------------
static __device__ __forceinline__ void mma_tf32(
    float* d, const uint32_t* a, uint32_t b0, uint32_t b1)
{
    asm volatile(
        "mma.sync.aligned.m16n8k8.row.col.f32.tf32.tf32.f32 "
        "{%0,%1,%2,%3},{%4,%5,%6,%7},{%8,%9},{%0,%1,%2,%3};"
        : "+f"(d[0]), "+f"(d[1]), "+f"(d[2]), "+f"(d[3])
        : "r"(a[0]), "r"(a[1]), "r"(a[2]), "r"(a[3]), "r"(b0), "r"(b1));
}

// ---------------------------------------------------------------------------
// Threefry-2x32 — exact JAX
// ---------------------------------------------------------------------------
static __host__ __device__ __forceinline__ uint32_t tf_rotl(uint32_t v, int r) {
    return (v << r) | (v >> (32 - r));
}
static __host__ __device__ __forceinline__ void threefry2x32(
    uint32_t k0, uint32_t k1, uint32_t x0, uint32_t x1,
    uint32_t& o0, uint32_t& o1)
{
    uint32_t ks2 = k0 ^ k1 ^ 0x1BD11BDAu;
    x0 += k0; x1 += k1;
    x0 += x1; x1 = tf_rotl(x1, 13); x1 ^= x0;
    x0 += x1; x1 = tf_rotl(x1, 15); x1 ^= x0;
    x0 += x1; x1 = tf_rotl(x1, 26); x1 ^= x0;
    x0 += x1; x1 = tf_rotl(x1,  6); x1 ^= x0;
    x0 += k1; x1 += ks2 + 1u;
    x0 += x1; x1 = tf_rotl(x1, 17); x1 ^= x0;
    x0 += x1; x1 = tf_rotl(x1, 29); x1 ^= x0;
    x0 += x1; x1 = tf_rotl(x1, 16); x1 ^= x0;
    x0 += x1; x1 = tf_rotl(x1, 24); x1 ^= x0;
    x0 += ks2; x1 += k0 + 2u;
    x0 += x1; x1 = tf_rotl(x1, 13); x1 ^= x0;
    x0 += x1; x1 = tf_rotl(x1, 15); x1 ^= x0;
    x0 += x1; x1 = tf_rotl(x1, 26); x1 ^= x0;
    x0 += x1; x1 = tf_rotl(x1,  6); x1 ^= x0;
    x0 += k0; x1 += k1 + 3u;
    x0 += x1; x1 = tf_rotl(x1, 17); x1 ^= x0;
    x0 += x1; x1 = tf_rotl(x1, 29); x1 ^= x0;
    x0 += x1; x1 = tf_rotl(x1, 16); x1 ^= x0;
    x0 += x1; x1 = tf_rotl(x1, 24); x1 ^= x0;
    x0 += k1; x1 += ks2 + 4u;
    x0 += x1; x1 = tf_rotl(x1, 13); x1 ^= x0;
    x0 += x1; x1 = tf_rotl(x1, 15); x1 ^= x0;
    x0 += x1; x1 = tf_rotl(x1, 26); x1 ^= x0;
    x0 += x1; x1 = tf_rotl(x1,  6); x1 ^= x0;
    x0 += ks2; x1 += k0 + 5u;
    o0 = x0; o1 = x1;
}

// ---------------------------------------------------------------------------
// Pack / maskall / prep / unpack
// ---------------------------------------------------------------------------
__global__ void nca_pack_kernel(const float* __restrict__ x)
{
    int p = blockIdx.x * 256 + threadIdx.x;
    if (blockIdx.x == 0 && threadIdx.x < STEPS) {
        g_cnt[threadIdx.x] = 0; g_icnt[threadIdx.x] = 0;
    }
    if (p >= NPIX) return;
    int b = p >> 16, hw = p & 65535;
    float v[CCH];
#pragma unroll
    for (int c = 0; c < CCH; ++c)
        v[c] = x[((size_t)(b * CCH + c) << 16) + hw];
    float4* dst = reinterpret_cast<float4*>(g_state[0] + ((size_t)p << 4));
    dst[0] = make_float4(v[0], v[1], v[2], v[3]);
    dst[1] = make_float4(v[4], v[5], v[6], v[7]);
    dst[2] = make_float4(v[8], v[9], v[10], v[11]);
    dst[3] = make_float4(v[12], v[13], v[14], v[15]);
}

__global__ void nca_maskall_kernel(KeyArr keys)
{
    int p = blockIdx.x * 256 + threadIdx.x;
    const int lane = threadIdx.x & 31;
#pragma unroll 1
    for (int s = 0; s < STEPS; ++s) {
        uint32_t r0, r1;
        threefry2x32(keys.k0[s], keys.k1[s], 0u, (uint32_t)p, r0, r1);
        uint32_t bits = r0 ^ r1;
        float u = __uint_as_float((bits >> 9) | 0x3f800000u) - 1.0f;
        bool active = (u <= 0.5f);
        unsigned ball = __ballot_sync(0xffffffffu, active);
        int nact = __popc(ball);
        int rank = __popc(ball & ((1u << lane) - 1u));
        int baseA = 0, baseI = 0;
        if (lane == 0) {
            if (nact > 0)  baseA = atomicAdd(&g_cnt[s], nact);
            if (nact < 32) baseI = atomicAdd(&g_icnt[s], 32 - nact);
        }
        baseA = __shfl_sync(0xffffffffu, baseA, 0);
        baseI = __shfl_sync(0xffffffffu, baseI, 0);
        if (active) g_list[s][baseA + rank] = p;
        else        g_ilist[s][baseI + (lane - rank)] = p;
    }
}

__global__ void nca_prep_kernel(const float* __restrict__ w_fc0)
{
    int i = blockIdx.x * 256 + threadIdx.x;
    if (i < HID * 48) {
        int n = i / 48, k = i % 48;
        uint32_t hi, lo; split_tf32(w_fc0[k * HID + n], hi, lo);
        g_w0t_hi[i] = __uint_as_float(hi);
        g_w0t_lo[i] = __uint_as_float(lo);
    }
}

__global__ void nca_unpack_kernel(float* __restrict__ out)
{
    int p = blockIdx.x * 256 + threadIdx.x;
    if (p >= NPIX) return;
    int b = p >> 16, hw = p & 65535;
    const float4* src = reinterpret_cast<const float4*>(g_state[0] + ((size_t)p << 4));
    float4 a0 = src[0], a1 = src[1], a2 = src[2], a3 = src[3];
    float v[CCH] = {a0.x,a0.y,a0.z,a0.w, a1.x,a1.y,a1.z,a1.w,
                    a2.x,a2.y,a2.z,a2.w, a3.x,a3.y,a3.z,a3.w};
    out[((size_t)b << 16) + hw] = v[3];
    float* xf = out + NPIX;
#pragma unroll
    for (int c = 0; c < CCH; ++c)
        xf[((size_t)(b * CCH + c) << 16) + hw] = v[c];
}

// ---------------------------------------------------------------------------
// SMEM layout (float offsets)
// ---------------------------------------------------------------------------
#define AP 52      // A/B row pad (48 data floats)
#define W1P 20
#define SM_BIAS 0                       // 128
#define SM_P0   128                     // 144
#define SM_P1   272                     // 144
#define SM_W1   416                     // 128*20 = 2560
#define SM_BH   (SM_W1 + 2560)          // 128*52 = 6656
#define SM_BL   (SM_BH + 6656)          // 6656
#define SM_AH   (SM_BL + 6656)          // 256*52 = 13312
#define SM_AL   (SM_AH + 13312)         // 13312
#define SM_DX   (SM_AL + 13312)         // 256*20 = 5120
#define SM_FLOATS (SM_DX + 5120)
#define SM_BYTES  (SM_FLOATS * 4)

// ---------------------------------------------------------------------------
// Step kernel: persistent 148 blocks x 256 threads; 256-px tiles.
// Quad-mapped I/O (4 lanes per pixel) with FULLY-UNROLLED gather phase so all
// 36 independent 16B LDGs are in flight together (MLP=36, coalesced).
// ---------------------------------------------------------------------------
__global__ void __launch_bounds__(256, 1)
nca_step_mma(int src, int step,
             const float* __restrict__ w_p0, const float* __restrict__ w_p1,
             const float* __restrict__ b_fc0, const float* __restrict__ w_fc1)
{
    extern __shared__ float sm[];
    float* s_bias = sm + SM_BIAS;
    float* s_p0   = sm + SM_P0;
    float* s_p1   = sm + SM_P1;
    float* s_W1   = sm + SM_W1;
    float* s_BH   = sm + SM_BH;
    float* s_BL   = sm + SM_BL;
    float* s_AH   = sm + SM_AH;
    float* s_AL   = sm + SM_AL;
    float* s_DX   = sm + SM_DX;

    const float* cur = g_state[src];
    float*       nxt = g_state[src ^ 1];
    const int tid  = threadIdx.x;
    const int lane = tid & 31;
    const int g  = lane >> 2;
    const int tg = lane & 3;
    const int R  = (tid >> 5) * 32;   // warp's GEMM row base
    const int Q   = tid >> 2;         // quad index (0..63)
    const int sub = tid & 3;          // channel-chunk owner (0..3)

    // ---- stage constants once ----
    if (tid < 128) s_bias[tid] = b_fc0[tid];
    if (tid < 144) { s_p0[tid] = w_p0[tid]; s_p1[tid] = w_p1[tid]; }
    for (int i = tid; i < HID * CCH; i += 256)
        s_W1[(i >> 4) * W1P + (i & 15)] = w_fc1[i];
    for (int i = tid; i < HID * 48; i += 256) {
        int n = i / 48, k = i % 48;
        s_BH[n * AP + k] = g_w0t_hi[i];
        s_BL[n * AP + k] = g_w0t_lo[i];
    }
    __syncthreads();

    const int count = g_cnt[step];
    const int* al = g_list[step];
    const int ntiles = (count + 255) >> 8;

    // per-thread tap weights (registers; uniform across quad row loop)
    u64 tw0[9][2], tw1[9][2];
#pragma unroll
    for (int tap = 0; tap < 9; ++tap) {
        ulonglong2 t0 = *reinterpret_cast<const ulonglong2*>(s_p0 + tap * 16 + sub * 4);
        ulonglong2 t1 = *reinterpret_cast<const ulonglong2*>(s_p1 + tap * 16 + sub * 4);
        tw0[tap][0] = t0.x; tw0[tap][1] = t0.y;
        tw1[tap][0] = t1.x; tw1[tap][1] = t1.y;
    }

#pragma unroll 1
    for (int tile = blockIdx.x; tile < ntiles; tile += NSM_BLOCKS) {

        // =========== phase 1: perception + A staging (quad-mapped) ===========
        // Fully unrolled over 4 rows: addresses first, then ALL loads (MLP=36),
        // then FMAs, then split+store.
        float cenr[4][4];
        int   pxr[4];
        {
            const float* addr[4][9];
#pragma unroll
            for (int r = 0; r < 4; ++r) {
                const int li = tile * 256 + r * 64 + Q;
                const int p  = al[(li < count) ? li : (count - 1)];
                pxr[r] = (li < count) ? p : -1;
                const float* base = cur + ((size_t)(p >> 16) << 20) + sub * 4;
                const int h = (p >> 8) & 255, w = p & 255;
#pragma unroll
                for (int dh = -1; dh <= 1; ++dh) {
                    int hh = h + dh; hh = (hh < 0) ? 1 : ((hh > 255) ? 254 : hh);
#pragma unroll
                    for (int dw = -1; dw <= 1; ++dw) {
                        int ww = w + dw; ww = (ww < 0) ? 1 : ((ww > 255) ? 254 : ww);
                        addr[r][(dh + 1) * 3 + (dw + 1)] =
                            base + (((size_t)((hh << 8) | ww)) << 4);
                    }
                }
            }

            // all 36 independent loads issued back-to-back
            u64 vx[4][9], vy[4][9];
#pragma unroll
            for (int r = 0; r < 4; ++r)
#pragma unroll
                for (int tap = 0; tap < 9; ++tap) {
                    ulonglong2 v = *reinterpret_cast<const ulonglong2*>(addr[r][tap]);
                    vx[r][tap] = v.x; vy[r][tap] = v.y;
                }

            // convolve + stage
#pragma unroll
            for (int r = 0; r < 4; ++r) {
                u64 c0a = 0ull, c0b = 0ull, c1a = 0ull, c1b = 0ull;
#pragma unroll
                for (int tap = 0; tap < 9; ++tap) {
                    ffma2(c0a, vx[r][tap], tw0[tap][0]);
                    ffma2(c0b, vy[r][tap], tw0[tap][1]);
                    ffma2(c1a, vx[r][tap], tw1[tap][0]);
                    ffma2(c1b, vy[r][tap], tw1[tap][1]);
                }
                float2 f0 = unpack2(vx[r][4]), f1 = unpack2(vy[r][4]);  // center tap
                float2 a0 = unpack2(c0a),  a1 = unpack2(c0b);
                float2 b0 = unpack2(c1a),  b1 = unpack2(c1b);
                cenr[r][0] = f0.x; cenr[r][1] = f0.y;
                cenr[r][2] = f1.x; cenr[r][3] = f1.y;

                const float vals[12] = {f0.x, f0.y, f1.x, f1.y,
                                        a0.x, a0.y, a1.x, a1.y,
                                        b0.x, b0.y, b1.x, b1.y};
                uint32_t hi[12], lo[12];
#pragma unroll
                for (int j = 0; j < 12; ++j) split_tf32(vals[j], hi[j], lo[j]);
                const int row = r * 64 + Q;
                float* ah  = s_AH + row * AP + sub * 4;
                float* alp = s_AL + row * AP + sub * 4;
#pragma unroll
                for (int c3 = 0; c3 < 3; ++c3) {
                    *reinterpret_cast<float4*>(ah + c3 * 16) = make_float4(
                        __uint_as_float(hi[4*c3]),   __uint_as_float(hi[4*c3+1]),
                        __uint_as_float(hi[4*c3+2]), __uint_as_float(hi[4*c3+3]));
                    *reinterpret_cast<float4*>(alp + c3 * 16) = make_float4(
                        __uint_as_float(lo[4*c3]),   __uint_as_float(lo[4*c3+1]),
                        __uint_as_float(lo[4*c3+2]), __uint_as_float(lo[4*c3+3]));
                }
            }
        }
        __syncthreads();

        // =========== phase 2: GEMM1 (mma tf32 x3) + epilogue + GEMM2 =========
        u64 dx2[2][2][8];
#pragma unroll
        for (int m = 0; m < 2; ++m)
#pragma unroll
            for (int r = 0; r < 2; ++r)
#pragma unroll
                for (int j = 0; j < 8; ++j) dx2[m][r][j] = 0ull;

#pragma unroll 1
        for (int nh = 0; nh < 2; ++nh) {
            float acc[2][8][4];
#pragma unroll
            for (int m = 0; m < 2; ++m)
#pragma unroll
                for (int nt = 0; nt < 8; ++nt)
#pragma unroll
                    for (int j = 0; j < 4; ++j) acc[m][nt][j] = 0.0f;

#pragma unroll 1
            for (int kt = 0; kt < 6; ++kt) {
                const int kc = kt * 8 + tg;
                uint32_t ah[2][4], alr[2][4];
#pragma unroll
                for (int m = 0; m < 2; ++m) {
                    const int r0 = R + m * 16 + g;
                    ah[m][0]  = __float_as_uint(s_AH[r0 * AP + kc]);
                    ah[m][1]  = __float_as_uint(s_AH[(r0 + 8) * AP + kc]);
                    ah[m][2]  = __float_as_uint(s_AH[r0 * AP + kc + 4]);
                    ah[m][3]  = __float_as_uint(s_AH[(r0 + 8) * AP + kc + 4]);
                    alr[m][0] = __float_as_uint(s_AL[r0 * AP + kc]);
                    alr[m][1] = __float_as_uint(s_AL[(r0 + 8) * AP + kc]);
                    alr[m][2] = __float_as_uint(s_AL[r0 * AP + kc + 4]);
                    alr[m][3] = __float_as_uint(s_AL[(r0 + 8) * AP + kc + 4]);
                }
#pragma unroll
                for (int nt = 0; nt < 8; ++nt) {
                    const int n = (nh * 8 + nt) * 8 + g;
                    uint32_t bh0 = __float_as_uint(s_BH[n * AP + kc]);
                    uint32_t bh1 = __float_as_uint(s_BH[n * AP + kc + 4]);
                    uint32_t bl0 = __float_as_uint(s_BL[n * AP + kc]);
                    uint32_t bl1 = __float_as_uint(s_BL[n * AP + kc + 4]);
#pragma unroll
                    for (int m = 0; m < 2; ++m) {
                        mma_tf32(acc[m][nt], ah[m],  bh0, bh1);
                        mma_tf32(acc[m][nt], ah[m],  bl0, bl1);
                        mma_tf32(acc[m][nt], alr[m], bh0, bh1);
                    }
                }
            }

#pragma unroll
            for (int nt = 0; nt < 8; ++nt) {
                const int t0 = nh * 64 + nt * 8 + 2 * tg;
                const float bf0 = s_bias[t0], bf1 = s_bias[t0 + 1];
                u64 wa[8], wb[8];
                {
                    const ulonglong2* w1a = reinterpret_cast<const ulonglong2*>(s_W1 + t0 * W1P);
                    const ulonglong2* w1b = reinterpret_cast<const ulonglong2*>(s_W1 + (t0 + 1) * W1P);
#pragma unroll
                    for (int q = 0; q < 4; ++q) {
                        ulonglong2 ta = w1a[q], tb = w1b[q];
                        wa[2*q] = ta.x; wa[2*q+1] = ta.y;
                        wb[2*q] = tb.x; wb[2*q+1] = tb.y;
                    }
                }
#pragma unroll
                for (int m = 0; m < 2; ++m) {
                    u64 H00 = pack2dup(fmaxf(acc[m][nt][0] + bf0, 0.0f));
                    u64 H01 = pack2dup(fmaxf(acc[m][nt][1] + bf1, 0.0f));
                    u64 H10 = pack2dup(fmaxf(acc[m][nt][2] + bf0, 0.0f));
                    u64 H11 = pack2dup(fmaxf(acc[m][nt][3] + bf1, 0.0f));
#pragma unroll
                    for (int j = 0; j < 8; ++j) {
                        ffma2(dx2[m][0][j], H00, wa[j]);
                        ffma2(dx2[m][0][j], H01, wb[j]);
                        ffma2(dx2[m][1][j], H10, wa[j]);
                        ffma2(dx2[m][1][j], H11, wb[j]);
                    }
                }
            }
        }

        // quad reduce + stage dx
#pragma unroll
        for (int m = 0; m < 2; ++m) {
#pragma unroll
            for (int r = 0; r < 2; ++r) {
                float red[16];
#pragma unroll
                for (int j = 0; j < 8; ++j) {
                    float2 f = unpack2(dx2[m][r][j]);
                    red[2*j] = f.x; red[2*j+1] = f.y;
                }
#pragma unroll
                for (int o = 0; o < 16; ++o) {
                    red[o] += __shfl_xor_sync(0xffffffffu, red[o], 1);
                    red[o] += __shfl_xor_sync(0xffffffffu, red[o], 2);
                }
                if (tg == 0) {
                    const int row = R + m * 16 + r * 8 + g;
                    float* d = s_DX + row * W1P;
                    *reinterpret_cast<float4*>(d +  0) = make_float4(red[0],  red[1],  red[2],  red[3]);
                    *reinterpret_cast<float4*>(d +  4) = make_float4(red[4],  red[5],  red[6],  red[7]);
                    *reinterpret_cast<float4*>(d +  8) = make_float4(red[8],  red[9],  red[10], red[11]);
                    *reinterpret_cast<float4*>(d + 12) = make_float4(red[12], red[13], red[14], red[15]);
                }
            }
        }
        __syncthreads();

        // =========== phase 3: residual update + store (quad-mapped) ==========
#pragma unroll
        for (int r = 0; r < 4; ++r) {
            if (pxr[r] < 0) continue;
            const int row = r * 64 + Q;
            float4 dx = *reinterpret_cast<float4*>(s_DX + row * W1P + sub * 4);
            float o0 = cenr[r][0] + dx.x;
            float o1 = cenr[r][1] + dx.y;
            float o2 = cenr[r][2] + dx.z;
            float o3 = cenr[r][3] + dx.w;
            if (sub == 0) { o0 = cenr[r][0]; o1 = cenr[r][1]; o2 = cenr[r][2]; }
            *reinterpret_cast<float4*>(nxt + ((size_t)pxr[r] << 4) + sub * 4) =
                make_float4(o0, o1, o2, o3);
        }
        __syncthreads();
    }

    // ---- inactive copy-through (quad-mapped: 16B per lane, full coverage) ----
    const int icnt = g_icnt[step];
    const int* il = g_ilist[step];
    const int itot = icnt * 4;
    for (int j = blockIdx.x * 256 + tid; j < itot; j += NSM_BLOCKS * 256) {
        int idx = j >> 2, s2 = j & 3;
        int p = il[idx];
        const float4 v = *reinterpret_cast<const float4*>(
            cur + ((size_t)p << 4) + s2 * 4);
        *reinterpret_cast<float4*>(nxt + ((size_t)p << 4) + s2 * 4) = v;
    }
}

// ---------------------------------------------------------------------------
// Launch
// ---------------------------------------------------------------------------
extern "C" void kernel_launch(void* const* d_in, const int* in_sizes, int n_in,
                              void* d_out, int out_size)
{
    const float* x      = (const float*)d_in[0];
    const float* w_p0   = (const float*)d_in[1];
    const float* w_p1   = (const float*)d_in[2];
    const float* w_fc0  = (const float*)d_in[3];
    const float* b_fc0  = (const float*)d_in[4];
    const float* w_fc1  = (const float*)d_in[5];
    float* out = (float*)d_out;

    KeyArr keys;
    for (int j = 0; j < STEPS; ++j) {
        uint32_t a, b;
        threefry2x32(0u, 42u, 0u, (uint32_t)j, a, b);
        keys.k0[j] = a; keys.k1[j] = b;
    }

    cudaFuncSetAttribute(nca_step_mma,
                         cudaFuncAttributeMaxDynamicSharedMemorySize, SM_BYTES);

    nca_pack_kernel<<<NPIX / 256, 256>>>(x);
    nca_maskall_kernel<<<NPIX / 256, 256>>>(keys);
    nca_prep_kernel<<<(HID * 48 + 255) / 256, 256>>>(w_fc0);
    for (int s = 0; s < STEPS; ++s) {
        nca_step_mma<<<NSM_BLOCKS, 256, SM_BYTES>>>(
            s & 1, s, w_p0, w_p1, b_fc0, w_fc1);
    }
    nca_unpack_kernel<<<NPIX / 256, 256>>>(out);
}

// round 15
// speedup vs baseline: 1.1566x; 1.0651x over previous
#include <cuda_runtime.h>
#include <cstdint>

// ---------------------------------------------------------------------------
// Problem constants
// ---------------------------------------------------------------------------
#define BATCH 8
#define IMG   256
#define CCH   16
#define HID   128
#define NPIX  (BATCH * IMG * IMG)
#define STATE_ELEMS (NPIX * CCH)
#define STEPS 32
#define LIST_CAP (NPIX / 2 + 8192)
#define NSM_BLOCKS 148
#define NWARPS 8

typedef unsigned long long u64;

__device__ float g_state[2][STATE_ELEMS];
__device__ int g_list[STEPS][LIST_CAP];
__device__ int g_ilist[STEPS][LIST_CAP];
__device__ int g_cnt[STEPS];
__device__ int g_icnt[STEPS];
// W0^T split into tf32 hi/lo: [n=128][k=48]
__device__ float g_w0t_hi[HID * 48];
__device__ float g_w0t_lo[HID * 48];

struct KeyArr { uint32_t k0[STEPS]; uint32_t k1[STEPS]; };

// ---------------------------------------------------------------------------
// packed f32x2 helpers (bit-exact: two independent rn fp32 FMAs)
// ---------------------------------------------------------------------------
static __device__ __forceinline__ u64 pack2dup(float x) {
    u64 r; asm("mov.b64 %0, {%1, %1};" : "=l"(r) : "f"(x)); return r;
}
static __device__ __forceinline__ void ffma2(u64& acc, u64 a, u64 b) {
    asm("fma.rn.f32x2 %0, %1, %2, %0;" : "+l"(acc) : "l"(a), "l"(b));
}
static __device__ __forceinline__ float2 unpack2(u64 v) {
    float2 f; asm("mov.b64 {%0, %1}, %2;" : "=f"(f.x), "=f"(f.y) : "l"(v)); return f;
}

// ---------------------------------------------------------------------------
// tf32 split
// ---------------------------------------------------------------------------
static __device__ __forceinline__ uint32_t cvt_tf32(float v) {
    uint32_t r; asm("cvt.rna.tf32.f32 %0, %1;" : "=r"(r) : "f"(v)); return r;
}
static __device__ __forceinline__ void split_tf32(float v, uint32_t& hi, uint32_t& lo) {
    hi = cvt_tf32(v);
    lo = cvt_tf32(v - __uint_as_float(hi));
}

// ---------------------------------------------------------------------------
// warp mma: m16n8k8 tf32 (sm_80 baseline PTX — legal on sm_103)
// ---------------------------------------------------------------------------
static __device__ __forceinline__ void mma_tf32(
    float* d, const uint32_t* a, uint32_t b0, uint32_t b1)
{
    asm volatile(
        "mma.sync.aligned.m16n8k8.row.col.f32.tf32.tf32.f32 "
        "{%0,%1,%2,%3},{%4,%5,%6,%7},{%8,%9},{%0,%1,%2,%3};"
        : "+f"(d[0]), "+f"(d[1]), "+f"(d[2]), "+f"(d[3])
        : "r"(a[0]), "r"(a[1]), "r"(a[2]), "r"(a[3]), "r"(b0), "r"(b1));
}

// ---------------------------------------------------------------------------
// Threefry-2x32 — exact JAX
// ---------------------------------------------------------------------------
static __host__ __device__ __forceinline__ uint32_t tf_rotl(uint32_t v, int r) {
    return (v << r) | (v >> (32 - r));
}
static __host__ __device__ __forceinline__ void threefry2x32(
    uint32_t k0, uint32_t k1, uint32_t x0, uint32_t x1,
    uint32_t& o0, uint32_t& o1)
{
    uint32_t ks2 = k0 ^ k1 ^ 0x1BD11BDAu;
    x0 += k0; x1 += k1;
    x0 += x1; x1 = tf_rotl(x1, 13); x1 ^= x0;
    x0 += x1; x1 = tf_rotl(x1, 15); x1 ^= x0;
    x0 += x1; x1 = tf_rotl(x1, 26); x1 ^= x0;
    x0 += x1; x1 = tf_rotl(x1,  6); x1 ^= x0;
    x0 += k1; x1 += ks2 + 1u;
    x0 += x1; x1 = tf_rotl(x1, 17); x1 ^= x0;
    x0 += x1; x1 = tf_rotl(x1, 29); x1 ^= x0;
    x0 += x1; x1 = tf_rotl(x1, 16); x1 ^= x0;
    x0 += x1; x1 = tf_rotl(x1, 24); x1 ^= x0;
    x0 += ks2; x1 += k0 + 2u;
    x0 += x1; x1 = tf_rotl(x1, 13); x1 ^= x0;
    x0 += x1; x1 = tf_rotl(x1, 15); x1 ^= x0;
    x0 += x1; x1 = tf_rotl(x1, 26); x1 ^= x0;
    x0 += x1; x1 = tf_rotl(x1,  6); x1 ^= x0;
    x0 += k0; x1 += k1 + 3u;
    x0 += x1; x1 = tf_rotl(x1, 17); x1 ^= x0;
    x0 += x1; x1 = tf_rotl(x1, 29); x1 ^= x0;
    x0 += x1; x1 = tf_rotl(x1, 16); x1 ^= x0;
    x0 += x1; x1 = tf_rotl(x1, 24); x1 ^= x0;
    x0 += k1; x1 += ks2 + 4u;
    x0 += x1; x1 = tf_rotl(x1, 13); x1 ^= x0;
    x0 += x1; x1 = tf_rotl(x1, 15); x1 ^= x0;
    x0 += x1; x1 = tf_rotl(x1, 26); x1 ^= x0;
    x0 += x1; x1 = tf_rotl(x1,  6); x1 ^= x0;
    x0 += ks2; x1 += k0 + 5u;
    o0 = x0; o1 = x1;
}

// ---------------------------------------------------------------------------
// Pack / maskall / prep / unpack
// ---------------------------------------------------------------------------
__global__ void nca_pack_kernel(const float* __restrict__ x)
{
    int p = blockIdx.x * 256 + threadIdx.x;
    if (blockIdx.x == 0 && threadIdx.x < STEPS) {
        g_cnt[threadIdx.x] = 0; g_icnt[threadIdx.x] = 0;
    }
    if (p >= NPIX) return;
    int b = p >> 16, hw = p & 65535;
    float v[CCH];
#pragma unroll
    for (int c = 0; c < CCH; ++c)
        v[c] = x[((size_t)(b * CCH + c) << 16) + hw];
    float4* dst = reinterpret_cast<float4*>(g_state[0] + ((size_t)p << 4));
    dst[0] = make_float4(v[0], v[1], v[2], v[3]);
    dst[1] = make_float4(v[4], v[5], v[6], v[7]);
    dst[2] = make_float4(v[8], v[9], v[10], v[11]);
    dst[3] = make_float4(v[12], v[13], v[14], v[15]);
}

__global__ void nca_maskall_kernel(KeyArr keys)
{
    int p = blockIdx.x * 256 + threadIdx.x;
    const int lane = threadIdx.x & 31;
#pragma unroll 1
    for (int s = 0; s < STEPS; ++s) {
        uint32_t r0, r1;
        threefry2x32(keys.k0[s], keys.k1[s], 0u, (uint32_t)p, r0, r1);
        uint32_t bits = r0 ^ r1;
        float u = __uint_as_float((bits >> 9) | 0x3f800000u) - 1.0f;
        bool active = (u <= 0.5f);
        unsigned ball = __ballot_sync(0xffffffffu, active);
        int nact = __popc(ball);
        int rank = __popc(ball & ((1u << lane) - 1u));
        int baseA = 0, baseI = 0;
        if (lane == 0) {
            if (nact > 0)  baseA = atomicAdd(&g_cnt[s], nact);
            if (nact < 32) baseI = atomicAdd(&g_icnt[s], 32 - nact);
        }
        baseA = __shfl_sync(0xffffffffu, baseA, 0);
        baseI = __shfl_sync(0xffffffffu, baseI, 0);
        if (active) g_list[s][baseA + rank] = p;
        else        g_ilist[s][baseI + (lane - rank)] = p;
    }
}

__global__ void nca_prep_kernel(const float* __restrict__ w_fc0)
{
    int i = blockIdx.x * 256 + threadIdx.x;
    if (i < HID * 48) {
        int n = i / 48, k = i % 48;
        uint32_t hi, lo; split_tf32(w_fc0[k * HID + n], hi, lo);
        g_w0t_hi[i] = __uint_as_float(hi);
        g_w0t_lo[i] = __uint_as_float(lo);
    }
}

__global__ void nca_unpack_kernel(float* __restrict__ out)
{
    int p = blockIdx.x * 256 + threadIdx.x;
    if (p >= NPIX) return;
    int b = p >> 16, hw = p & 65535;
    const float4* src = reinterpret_cast<const float4*>(g_state[0] + ((size_t)p << 4));
    float4 a0 = src[0], a1 = src[1], a2 = src[2], a3 = src[3];
    float v[CCH] = {a0.x,a0.y,a0.z,a0.w, a1.x,a1.y,a1.z,a1.w,
                    a2.x,a2.y,a2.z,a2.w, a3.x,a3.y,a3.z,a3.w};
    out[((size_t)b << 16) + hw] = v[3];
    float* xf = out + NPIX;
#pragma unroll
    for (int c = 0; c < CCH; ++c)
        xf[((size_t)(b * CCH + c) << 16) + hw] = v[c];
}

// ---------------------------------------------------------------------------
// SMEM layout (float offsets)
// ---------------------------------------------------------------------------
#define AP 52      // A/B row pad (48 data floats)
#define W1P 20
#define SM_BIAS 0                       // 128
#define SM_P0   128                     // 144
#define SM_P1   272                     // 144
#define SM_W1   416                     // 128*20 = 2560
#define SM_BH   (SM_W1 + 2560)          // 128*52 = 6656
#define SM_BL   (SM_BH + 6656)          // 6656
#define SM_AH   (SM_BL + 6656)          // 256*52 = 13312
#define SM_AL   (SM_AH + 13312)         // 13312
#define SM_DX   (SM_AL + 13312)         // 256*20 = 5120
#define SM_FLOATS (SM_DX + 5120)
#define SM_BYTES  (SM_FLOATS * 4)

// ---------------------------------------------------------------------------
// Step kernel: persistent 148 blocks x 256 threads; 32-px WARP-tiles.
// Each warp is fully autonomous in the tile loop (only __syncwarp): its GEMM
// rows 32w..32w+31 are exactly the rows its own lanes stage -> no block sync.
// ---------------------------------------------------------------------------
__global__ void __launch_bounds__(256, 1)
nca_step_mma(int src, int step,
             const float* __restrict__ w_p0, const float* __restrict__ w_p1,
             const float* __restrict__ b_fc0, const float* __restrict__ w_fc1)
{
    extern __shared__ float sm[];
    float* s_bias = sm + SM_BIAS;
    float* s_p0   = sm + SM_P0;
    float* s_p1   = sm + SM_P1;
    float* s_W1   = sm + SM_W1;
    float* s_BH   = sm + SM_BH;
    float* s_BL   = sm + SM_BL;
    float* s_AH   = sm + SM_AH;
    float* s_AL   = sm + SM_AL;
    float* s_DX   = sm + SM_DX;

    const float* cur = g_state[src];
    float*       nxt = g_state[src ^ 1];
    const int tid  = threadIdx.x;
    const int lane = tid & 31;
    const int warp = tid >> 5;
    const int g  = lane >> 2;
    const int tg = lane & 3;
    const int R  = warp * 32;         // warp's private A/DX row window
    const int qi  = lane >> 2;        // quad index within warp (0..7)
    const int sub = lane & 3;         // channel-chunk owner (0..3)

    // ---- stage constants once (block-wide, single sync) ----
    if (tid < 128) s_bias[tid] = b_fc0[tid];
    if (tid < 144) { s_p0[tid] = w_p0[tid]; s_p1[tid] = w_p1[tid]; }
    for (int i = tid; i < HID * CCH; i += 256)
        s_W1[(i >> 4) * W1P + (i & 15)] = w_fc1[i];
    for (int i = tid; i < HID * 48; i += 256) {
        int n = i / 48, k = i % 48;
        s_BH[n * AP + k] = g_w0t_hi[i];
        s_BL[n * AP + k] = g_w0t_lo[i];
    }
    __syncthreads();

    const int count = g_cnt[step];
    const int* al = g_list[step];
    const int ntiles = (count + 31) >> 5;          // 32-px warp tiles
    const int gwarp  = blockIdx.x * NWARPS + warp; // global warp id
    const int nwtot  = NSM_BLOCKS * NWARPS;

    // per-thread tap weights in registers
    u64 tw0[9][2], tw1[9][2];
#pragma unroll
    for (int tap = 0; tap < 9; ++tap) {
        ulonglong2 t0 = *reinterpret_cast<const ulonglong2*>(s_p0 + tap * 16 + sub * 4);
        ulonglong2 t1 = *reinterpret_cast<const ulonglong2*>(s_p1 + tap * 16 + sub * 4);
        tw0[tap][0] = t0.x; tw0[tap][1] = t0.y;
        tw1[tap][0] = t1.x; tw1[tap][1] = t1.y;
    }

#pragma unroll 1
    for (int wt = gwarp; wt < ntiles; wt += nwtot) {

        // =========== phase 1: perception + A staging (quad-mapped) ===========
        float cenr[4][4];
        int   pxr[4];
        {
            const float* addr[4][9];
#pragma unroll
            for (int r = 0; r < 4; ++r) {
                const int li = wt * 32 + r * 8 + qi;
                const int p  = al[(li < count) ? li : (count - 1)];
                pxr[r] = (li < count) ? p : -1;
                const float* base = cur + ((size_t)(p >> 16) << 20) + sub * 4;
                const int h = (p >> 8) & 255, w = p & 255;
#pragma unroll
                for (int dh = -1; dh <= 1; ++dh) {
                    int hh = h + dh; hh = (hh < 0) ? 1 : ((hh > 255) ? 254 : hh);
#pragma unroll
                    for (int dw = -1; dw <= 1; ++dw) {
                        int ww = w + dw; ww = (ww < 0) ? 1 : ((ww > 255) ? 254 : ww);
                        addr[r][(dh + 1) * 3 + (dw + 1)] =
                            base + (((size_t)((hh << 8) | ww)) << 4);
                    }
                }
            }

            // all 36 independent loads in flight together
            u64 vx[4][9], vy[4][9];
#pragma unroll
            for (int r = 0; r < 4; ++r)
#pragma unroll
                for (int tap = 0; tap < 9; ++tap) {
                    ulonglong2 v = *reinterpret_cast<const ulonglong2*>(addr[r][tap]);
                    vx[r][tap] = v.x; vy[r][tap] = v.y;
                }

            // convolve + stage to this warp's A rows
#pragma unroll
            for (int r = 0; r < 4; ++r) {
                u64 c0a = 0ull, c0b = 0ull, c1a = 0ull, c1b = 0ull;
#pragma unroll
                for (int tap = 0; tap < 9; ++tap) {
                    ffma2(c0a, vx[r][tap], tw0[tap][0]);
                    ffma2(c0b, vy[r][tap], tw0[tap][1]);
                    ffma2(c1a, vx[r][tap], tw1[tap][0]);
                    ffma2(c1b, vy[r][tap], tw1[tap][1]);
                }
                float2 f0 = unpack2(vx[r][4]), f1 = unpack2(vy[r][4]);
                float2 a0 = unpack2(c0a),  a1 = unpack2(c0b);
                float2 b0 = unpack2(c1a),  b1 = unpack2(c1b);
                cenr[r][0] = f0.x; cenr[r][1] = f0.y;
                cenr[r][2] = f1.x; cenr[r][3] = f1.y;

                const float vals[12] = {f0.x, f0.y, f1.x, f1.y,
                                        a0.x, a0.y, a1.x, a1.y,
                                        b0.x, b0.y, b1.x, b1.y};
                uint32_t hi[12], lo[12];
#pragma unroll
                for (int j = 0; j < 12; ++j) split_tf32(vals[j], hi[j], lo[j]);
                const int row = R + r * 8 + qi;
                float* ah  = s_AH + row * AP + sub * 4;
                float* alp = s_AL + row * AP + sub * 4;
#pragma unroll
                for (int c3 = 0; c3 < 3; ++c3) {
                    *reinterpret_cast<float4*>(ah + c3 * 16) = make_float4(
                        __uint_as_float(hi[4*c3]),   __uint_as_float(hi[4*c3+1]),
                        __uint_as_float(hi[4*c3+2]), __uint_as_float(hi[4*c3+3]));
                    *reinterpret_cast<float4*>(alp + c3 * 16) = make_float4(
                        __uint_as_float(lo[4*c3]),   __uint_as_float(lo[4*c3+1]),
                        __uint_as_float(lo[4*c3+2]), __uint_as_float(lo[4*c3+3]));
                }
            }
        }
        __syncwarp();

        // =========== phase 2: GEMM1 (mma tf32 x3) + epilogue + GEMM2 =========
        u64 dx2[2][2][8];
#pragma unroll
        for (int m = 0; m < 2; ++m)
#pragma unroll
            for (int r = 0; r < 2; ++r)
#pragma unroll
                for (int j = 0; j < 8; ++j) dx2[m][r][j] = 0ull;

#pragma unroll 1
        for (int nh = 0; nh < 2; ++nh) {
            float acc[2][8][4];
#pragma unroll
            for (int m = 0; m < 2; ++m)
#pragma unroll
                for (int nt = 0; nt < 8; ++nt)
#pragma unroll
                    for (int j = 0; j < 4; ++j) acc[m][nt][j] = 0.0f;

#pragma unroll 1
            for (int kt = 0; kt < 6; ++kt) {
                const int kc = kt * 8 + tg;
                uint32_t ah[2][4], alr[2][4];
#pragma unroll
                for (int m = 0; m < 2; ++m) {
                    const int r0 = R + m * 16 + g;
                    ah[m][0]  = __float_as_uint(s_AH[r0 * AP + kc]);
                    ah[m][1]  = __float_as_uint(s_AH[(r0 + 8) * AP + kc]);
                    ah[m][2]  = __float_as_uint(s_AH[r0 * AP + kc + 4]);
                    ah[m][3]  = __float_as_uint(s_AH[(r0 + 8) * AP + kc + 4]);
                    alr[m][0] = __float_as_uint(s_AL[r0 * AP + kc]);
                    alr[m][1] = __float_as_uint(s_AL[(r0 + 8) * AP + kc]);
                    alr[m][2] = __float_as_uint(s_AL[r0 * AP + kc + 4]);
                    alr[m][3] = __float_as_uint(s_AL[(r0 + 8) * AP + kc + 4]);
                }
#pragma unroll
                for (int nt = 0; nt < 8; ++nt) {
                    const int n = (nh * 8 + nt) * 8 + g;
                    uint32_t bh0 = __float_as_uint(s_BH[n * AP + kc]);
                    uint32_t bh1 = __float_as_uint(s_BH[n * AP + kc + 4]);
                    uint32_t bl0 = __float_as_uint(s_BL[n * AP + kc]);
                    uint32_t bl1 = __float_as_uint(s_BL[n * AP + kc + 4]);
#pragma unroll
                    for (int m = 0; m < 2; ++m) {
                        mma_tf32(acc[m][nt], ah[m],  bh0, bh1);
                        mma_tf32(acc[m][nt], ah[m],  bl0, bl1);
                        mma_tf32(acc[m][nt], alr[m], bh0, bh1);
                    }
                }
            }

#pragma unroll
            for (int nt = 0; nt < 8; ++nt) {
                const int t0 = nh * 64 + nt * 8 + 2 * tg;
                const float bf0 = s_bias[t0], bf1 = s_bias[t0 + 1];
                u64 wa[8], wb[8];
                {
                    const ulonglong2* w1a = reinterpret_cast<const ulonglong2*>(s_W1 + t0 * W1P);
                    const ulonglong2* w1b = reinterpret_cast<const ulonglong2*>(s_W1 + (t0 + 1) * W1P);
#pragma unroll
                    for (int q = 0; q < 4; ++q) {
                        ulonglong2 ta = w1a[q], tb = w1b[q];
                        wa[2*q] = ta.x; wa[2*q+1] = ta.y;
                        wb[2*q] = tb.x; wb[2*q+1] = tb.y;
                    }
                }
#pragma unroll
                for (int m = 0; m < 2; ++m) {
                    u64 H00 = pack2dup(fmaxf(acc[m][nt][0] + bf0, 0.0f));
                    u64 H01 = pack2dup(fmaxf(acc[m][nt][1] + bf1, 0.0f));
                    u64 H10 = pack2dup(fmaxf(acc[m][nt][2] + bf0, 0.0f));
                    u64 H11 = pack2dup(fmaxf(acc[m][nt][3] + bf1, 0.0f));
#pragma unroll
                    for (int j = 0; j < 8; ++j) {
                        ffma2(dx2[m][0][j], H00, wa[j]);
                        ffma2(dx2[m][0][j], H01, wb[j]);
                        ffma2(dx2[m][1][j], H10, wa[j]);
                        ffma2(dx2[m][1][j], H11, wb[j]);
                    }
                }
            }
        }

        // quad reduce + stage dx (warp-private rows)
#pragma unroll
        for (int m = 0; m < 2; ++m) {
#pragma unroll
            for (int r = 0; r < 2; ++r) {
                float red[16];
#pragma unroll
                for (int j = 0; j < 8; ++j) {
                    float2 f = unpack2(dx2[m][r][j]);
                    red[2*j] = f.x; red[2*j+1] = f.y;
                }
#pragma unroll
                for (int o = 0; o < 16; ++o) {
                    red[o] += __shfl_xor_sync(0xffffffffu, red[o], 1);
                    red[o] += __shfl_xor_sync(0xffffffffu, red[o], 2);
                }
                if (tg == 0) {
                    const int row = R + m * 16 + r * 8 + g;
                    float* d = s_DX + row * W1P;
                    *reinterpret_cast<float4*>(d +  0) = make_float4(red[0],  red[1],  red[2],  red[3]);
                    *reinterpret_cast<float4*>(d +  4) = make_float4(red[4],  red[5],  red[6],  red[7]);
                    *reinterpret_cast<float4*>(d +  8) = make_float4(red[8],  red[9],  red[10], red[11]);
                    *reinterpret_cast<float4*>(d + 12) = make_float4(red[12], red[13], red[14], red[15]);
                }
            }
        }
        __syncwarp();

        // =========== phase 3: residual update + store (quad-mapped) ==========
#pragma unroll
        for (int r = 0; r < 4; ++r) {
            if (pxr[r] < 0) continue;
            const int row = R + r * 8 + qi;
            float4 dx = *reinterpret_cast<float4*>(s_DX + row * W1P + sub * 4);
            float o0 = cenr[r][0] + dx.x;
            float o1 = cenr[r][1] + dx.y;
            float o2 = cenr[r][2] + dx.z;
            float o3 = cenr[r][3] + dx.w;
            if (sub == 0) { o0 = cenr[r][0]; o1 = cenr[r][1]; o2 = cenr[r][2]; }
            *reinterpret_cast<float4*>(nxt + ((size_t)pxr[r] << 4) + sub * 4) =
                make_float4(o0, o1, o2, o3);
        }
        __syncwarp();
    }

    // ---- inactive copy-through (quad-mapped: 16B per lane, full coverage) ----
    const int icnt = g_icnt[step];
    const int* il = g_ilist[step];
    const int itot = icnt * 4;
    for (int j = blockIdx.x * 256 + tid; j < itot; j += NSM_BLOCKS * 256) {
        int idx = j >> 2, s2 = j & 3;
        int p = il[idx];
        const float4 v = *reinterpret_cast<const float4*>(
            cur + ((size_t)p << 4) + s2 * 4);
        *reinterpret_cast<float4*>(nxt + ((size_t)p << 4) + s2 * 4) = v;
    }
}

// ---------------------------------------------------------------------------
// Launch
// ---------------------------------------------------------------------------
extern "C" void kernel_launch(void* const* d_in, const int* in_sizes, int n_in,
                              void* d_out, int out_size)
{
    const float* x      = (const float*)d_in[0];
    const float* w_p0   = (const float*)d_in[1];
    const float* w_p1   = (const float*)d_in[2];
    const float* w_fc0  = (const float*)d_in[3];
    const float* b_fc0  = (const float*)d_in[4];
    const float* w_fc1  = (const float*)d_in[5];
    float* out = (float*)d_out;

    KeyArr keys;
    for (int j = 0; j < STEPS; ++j) {
        uint32_t a, b;
        threefry2x32(0u, 42u, 0u, (uint32_t)j, a, b);
        keys.k0[j] = a; keys.k1[j] = b;
    }

    cudaFuncSetAttribute(nca_step_mma,
                         cudaFuncAttributeMaxDynamicSharedMemorySize, SM_BYTES);

    nca_pack_kernel<<<NPIX / 256, 256>>>(x);
    nca_maskall_kernel<<<NPIX / 256, 256>>>(keys);
    nca_prep_kernel<<<(HID * 48 + 255) / 256, 256>>>(w_fc0);
    for (int s = 0; s < STEPS; ++s) {
        nca_step_mma<<<NSM_BLOCKS, 256, SM_BYTES>>>(
            s & 1, s, w_p0, w_p1, b_fc0, w_fc1);
    }
    nca_unpack_kernel<<<NPIX / 256, 256>>>(out);
}